// round 10
// baseline (speedup 1.0000x reference)
#include <cuda_runtime.h>
#include <math.h>
#include <stdint.h>

// ---------------------------------------------------------------------------
// EdgeMLPMPN via IMMA m16n8k32 s8 "emulated int16" GEMM.
// q = 256*ah + al (s8 hi/lo, ~15-bit fixed point); 3 passes:
//   acc1 += ah*bh ; acc2 += ah*bl + al*bh   (s32, exact)
//   value = s_a*s_b*(65536*acc1 + 256*acc2)   (al*bl dropped, ~1e-4 rel)
// Fragments for s8 k32 are byte-identical to f16 k16 ldmatrix layout.
// EPT=64, 2 CTAs/SM, 8 warps (4m x 2n). W double-buffered, one-shot stages.
// ---------------------------------------------------------------------------

#define EPT 64
#define THREADS 256
#define NMAX 100000
#define QMAX 32400.0f
#define SA1 272   // A1 row stride (256 s8 + 16 pad)
#define SA2 144   // h1 row stride (128 s8 + 16 pad)
#define SWS 144   // W chunk row stride (128 s8 + 16 pad)

#define SM_A_HI 0
#define SM_A_LO 17408                  // 64*272
#define SM_W    34816                  // 2 bufs x (hi 18432 | lo 18432)
#define WBUF_STRIDE 36864
#define WLO_OFF 18432
#define SM_CTRL (SM_W + 73728)         // 108544
#define SM_SIDS (SM_CTRL)
#define SM_B1   (SM_CTRL + 512)
#define SM_B2   (SM_B1 + 512)
#define SM_W3   (SM_B2 + 512)
#define SM_R0   (SM_W3 + 512)
#define SM_R1   (SM_R0 + 256)
#define SM_HMAX (SM_R1 + 256)
#define SMEM_BYTES (SM_HMAX + 16)      // ~108.6 KB -> 2 CTAs/SM

__device__ int g_is64;
__device__ unsigned g_xmax = 0, g_w1max = 0, g_w2max = 0;   // float bits, >=0
__device__ __align__(16) signed char g_x_hi[NMAX * 128];
__device__ __align__(16) signed char g_x_lo[NMAX * 128];
__device__ __align__(16) signed char g_w1q_hi[128 * 256];   // W1T[n][k]
__device__ __align__(16) signed char g_w1q_lo[128 * 256];
__device__ __align__(16) signed char g_w2q_hi[128 * 128];   // W2T[n][k]
__device__ __align__(16) signed char g_w2q_lo[128 * 128];

__device__ __forceinline__ uint32_t smem_u32(const void* p) {
    uint32_t a;
    asm("{ .reg .u64 t; cvta.to.shared.u64 t, %1; cvt.u32.u64 %0, t; }" : "=r"(a) : "l"(p));
    return a;
}
__device__ __forceinline__ void ldm_x4(uint32_t addr, uint32_t r[4]) {
    asm volatile("ldmatrix.sync.aligned.m8n8.x4.shared.b16 {%0,%1,%2,%3}, [%4];"
                 : "=r"(r[0]), "=r"(r[1]), "=r"(r[2]), "=r"(r[3]) : "r"(addr));
}
__device__ __forceinline__ void imma(int c[4], const uint32_t a[4],
                                     uint32_t b0, uint32_t b1) {
    asm volatile(
        "mma.sync.aligned.m16n8k32.row.col.s32.s8.s8.s32 "
        "{%0,%1,%2,%3}, {%4,%5,%6,%7}, {%8,%9}, {%0,%1,%2,%3};"
        : "+r"(c[0]), "+r"(c[1]), "+r"(c[2]), "+r"(c[3])
        : "r"(a[0]), "r"(a[1]), "r"(a[2]), "r"(a[3]), "r"(b0), "r"(b1));
}
__device__ __forceinline__ void cp16(uint32_t dst, const void* src) {
    asm volatile("cp.async.cg.shared.global [%0], [%1], 16;" :: "r"(dst), "l"(src));
}
__device__ __forceinline__ void cp_commit() {
    asm volatile("cp.async.commit_group;" ::: "memory");
}
__device__ __forceinline__ void cp_wait0() {
    asm volatile("cp.async.wait_group 0;" ::: "memory");
}
__device__ __forceinline__ float elu1(float v) { return v > 0.0f ? v : expm1f(v); }

// split q (|q|<=32511) into s8 hi/lo: q = 256*ah + al
__device__ __forceinline__ void split16(int q, int& ah, int& al) {
    ah = (q + 128) >> 8;
    al = q - (ah << 8);
}
__device__ __forceinline__ int quant(float v, float inv_s) {
    int q = __float2int_rn(v * inv_s);
    return max(-32511, min(32511, q));
}
__device__ __forceinline__ uint32_t pack4(int b0, int b1, int b2, int b3) {
    return (uint32_t)(b0 & 0xFF) | ((uint32_t)(b1 & 0xFF) << 8) |
           ((uint32_t)(b2 & 0xFF) << 16) | ((uint32_t)(b3 & 0xFF) << 24);
}

// ---------------- prologue 1: absmax reductions + dtype sniff ----------------
__global__ void absmax_kernel(const float* __restrict__ x, int n4,
                              const float* __restrict__ W1,
                              const float* __restrict__ W2,
                              const int* __restrict__ ei32) {
    __shared__ float wmax[32];
    int tid = threadIdx.x;
    if (blockIdx.x == 0 && tid == 0) {
        int odd_or = 0;
#pragma unroll
        for (int j = 1; j < 64; j += 2) odd_or |= ei32[j];
        g_is64 = (odd_or == 0) ? 1 : 0;
    }
    float lm = 0.0f;
    for (int i = blockIdx.x * blockDim.x + tid; i < n4; i += gridDim.x * blockDim.x) {
        float4 v = __ldg(reinterpret_cast<const float4*>(x) + i);
        lm = fmaxf(lm, fmaxf(fmaxf(fabsf(v.x), fabsf(v.y)), fmaxf(fabsf(v.z), fabsf(v.w))));
    }
#pragma unroll
    for (int o = 16; o > 0; o >>= 1) lm = fmaxf(lm, __shfl_xor_sync(0xffffffff, lm, o));
    if ((tid & 31) == 0) wmax[tid >> 5] = lm;
    __syncthreads();
    if (tid < 32) {
        float m = (tid < (int)(blockDim.x >> 5)) ? wmax[tid] : 0.0f;
#pragma unroll
        for (int o = 16; o > 0; o >>= 1) m = fmaxf(m, __shfl_xor_sync(0xffffffff, m, o));
        if (tid == 0) atomicMax(&g_xmax, __float_as_uint(m));
    }
    if (blockIdx.x == 0) {
        float m1 = 0.0f, m2 = 0.0f;
        for (int i = tid; i < 32768; i += blockDim.x) m1 = fmaxf(m1, fabsf(__ldg(W1 + i)));
        for (int i = tid; i < 16384; i += blockDim.x) m2 = fmaxf(m2, fabsf(__ldg(W2 + i)));
#pragma unroll
        for (int o = 16; o > 0; o >>= 1) {
            m1 = fmaxf(m1, __shfl_xor_sync(0xffffffff, m1, o));
            m2 = fmaxf(m2, __shfl_xor_sync(0xffffffff, m2, o));
        }
        if ((tid & 31) == 0) {
            atomicMax(&g_w1max, __float_as_uint(m1));
            atomicMax(&g_w2max, __float_as_uint(m2));
        }
    }
}

// ---------------- prologue 2: quantize x (split) + W1T/W2T (transpose+split) --
__global__ void quant_kernel(const float* __restrict__ x, int n4,
                             const float* __restrict__ W1,
                             const float* __restrict__ W2) {
    int i = blockIdx.x * blockDim.x + threadIdx.x;
    if (i < n4) {
        float inv = QMAX / fmaxf(__uint_as_float(g_xmax), 1e-20f);
        float4 v = __ldg(reinterpret_cast<const float4*>(x) + i);
        int q0 = quant(v.x, inv), q1 = quant(v.y, inv), q2 = quant(v.z, inv), q3 = quant(v.w, inv);
        int h0, l0, h1_, l1, h2, l2, h3, l3;
        split16(q0, h0, l0); split16(q1, h1_, l1); split16(q2, h2, l2); split16(q3, h3, l3);
        reinterpret_cast<uint32_t*>(g_x_hi)[i] = pack4(h0, h1_, h2, h3);
        reinterpret_cast<uint32_t*>(g_x_lo)[i] = pack4(l0, l1, l2, l3);
    } else if (i < n4 + 8192) {            // W1T [128 n][256 k], 4 k per thread
        int j = i - n4;
        int n = j >> 6, k4 = (j & 63) << 2;
        float inv = QMAX / fmaxf(__uint_as_float(g_w1max), 1e-20f);
        int h[4], l[4];
#pragma unroll
        for (int t = 0; t < 4; t++) {
            int q = quant(__ldg(W1 + (k4 + t) * 128 + n), inv);
            split16(q, h[t], l[t]);
        }
        reinterpret_cast<uint32_t*>(g_w1q_hi)[j] = pack4(h[0], h[1], h[2], h[3]);
        reinterpret_cast<uint32_t*>(g_w1q_lo)[j] = pack4(l[0], l[1], l[2], l[3]);
    } else if (i < n4 + 8192 + 4096) {     // W2T [128 n][128 k]
        int j = i - n4 - 8192;
        int n = j >> 5, k4 = (j & 31) << 2;
        float inv = QMAX / fmaxf(__uint_as_float(g_w2max), 1e-20f);
        int h[4], l[4];
#pragma unroll
        for (int t = 0; t < 4; t++) {
            int q = quant(__ldg(W2 + (k4 + t) * 128 + n), inv);
            split16(q, h[t], l[t]);
        }
        reinterpret_cast<uint32_t*>(g_w2q_hi)[j] = pack4(h[0], h[1], h[2], h[3]);
        reinterpret_cast<uint32_t*>(g_w2q_lo)[j] = pack4(l[0], l[1], l[2], l[3]);
    }
}

// stage one [128 n][128B k] hi/lo W chunk into buf
__device__ __forceinline__ void stage_w(uint32_t sb, int buf,
                                        const signed char* __restrict__ gh,
                                        const signed char* __restrict__ gl,
                                        int row_bytes, int col0, int tid) {
    uint32_t base = sb + SM_W + (uint32_t)buf * WBUF_STRIDE;
#pragma unroll
    for (int it = 0; it < 4; it++) {
        int idx = tid + it * THREADS;      // 0..1023
        int n = idx >> 3, j = idx & 7;
        cp16(base + n * SWS + j * 16, gh + n * row_bytes + col0 + j * 16);
        cp16(base + WLO_OFF + n * SWS + j * 16, gl + n * row_bytes + col0 + j * 16);
    }
    cp_commit();
}

// one 128B-k chunk (4 k-tiles of 32B): 3-pass IMMA into acc1 (hh), acc2 (hl+lh)
__device__ __forceinline__ void gemm_chunk(uint32_t sb, int buf, int sa, int a_k0byte,
                                           int e0, int n0, int lane,
                                           int acc1[8][4], int acc2[8][4]) {
    const int rowA = lane & 15;
    const int chA = (lane >> 4) * 16;
    const int rowB = (lane & 7) + ((lane >> 4) << 3);
    const int chB = ((lane >> 3) & 1) * 16;

    uint32_t aH = sb + SM_A_HI + (e0 + rowA) * sa + chA + a_k0byte;
    uint32_t aL = sb + SM_A_LO + (e0 + rowA) * sa + chA + a_k0byte;
    uint32_t wb = sb + SM_W + (uint32_t)buf * WBUF_STRIDE;
    uint32_t bH = wb + (n0 + rowB) * SWS + chB;
    uint32_t bL = bH + WLO_OFF;

#pragma unroll
    for (int kt = 0; kt < 4; kt++) {
        uint32_t ah[4], al[4];
        ldm_x4(aH + kt * 32, ah);
        ldm_x4(aL + kt * 32, al);
#pragma unroll
        for (int g = 0; g < 2; g++) {
            uint32_t bh0[4], bh1[4], bl0[4], bl1[4];
            ldm_x4(bH + (2 * g + 0) * 16 * SWS + kt * 32, bh0);
            ldm_x4(bH + (2 * g + 1) * 16 * SWS + kt * 32, bh1);
            ldm_x4(bL + (2 * g + 0) * 16 * SWS + kt * 32, bl0);
            ldm_x4(bL + (2 * g + 1) * 16 * SWS + kt * 32, bl1);
            int (*a1)[4] = &acc1[4 * g];
            int (*a2)[4] = &acc2[4 * g];
            imma(a1[0], ah, bh0[0], bh0[1]);
            imma(a1[1], ah, bh0[2], bh0[3]);
            imma(a1[2], ah, bh1[0], bh1[1]);
            imma(a1[3], ah, bh1[2], bh1[3]);
            imma(a2[0], ah, bl0[0], bl0[1]);
            imma(a2[1], ah, bl0[2], bl0[3]);
            imma(a2[2], ah, bl1[0], bl1[1]);
            imma(a2[3], ah, bl1[2], bl1[3]);
            imma(a2[0], al, bh0[0], bh0[1]);
            imma(a2[1], al, bh0[2], bh0[3]);
            imma(a2[2], al, bh1[0], bh1[1]);
            imma(a2[3], al, bh1[2], bh1[3]);
        }
    }
}

__global__ void __launch_bounds__(THREADS, 2)
edge_mlp_imma_kernel(const void* __restrict__ ei,
                     const float* __restrict__ b1, const float* __restrict__ b2,
                     const float* __restrict__ W3, const float* __restrict__ b3,
                     float* __restrict__ out, int n_edges, int n_nodes) {
    extern __shared__ char smem[];
    const uint32_t sb = smem_u32(smem);
    const int tid = threadIdx.x, wid = tid >> 5, lane = tid & 31;
    const int gid = lane >> 2, tig = lane & 3;
    const int mw = wid >> 1, nw = wid & 1;
    const int e0 = mw * 16, n0 = nw * 64;
    const int tile = blockIdx.x * EPT;
    const int nv = min(EPT, n_edges - tile);

    const bool is64 = (g_is64 != 0);
    const int* ei32 = (const int*)ei;
    const long long* ei64 = (const long long*)ei;

    int* sids = (int*)(smem + SM_SIDS);
    float* b1s = (float*)(smem + SM_B1);
    float* b2s = (float*)(smem + SM_B2);
    float* w3s = (float*)(smem + SM_W3);
    unsigned* hmax = (unsigned*)(smem + SM_HMAX);
    const int ncl = min(n_nodes, NMAX);
    if (tid == 0) hmax[0] = 0;
    if (tid < 128) {
        int half = tid >> 6, e = tid & 63;
        int ec = e < nv ? e : (nv - 1);
        int pos = half * n_edges + tile + ec;
        long long node = is64 ? ei64[pos] : (long long)ei32[pos];
        node = node < 0 ? 0 : (node >= ncl ? (long long)ncl - 1 : node);
        sids[tid] = (int)node;
        b1s[tid] = __ldg(b1 + tid);
        b2s[tid] = __ldg(b2 + tid);
        w3s[tid] = __ldg(W3 + tid);
    }
    const float s_x = fmaxf(__uint_as_float(g_xmax), 1e-20f) / QMAX;
    const float s_w1 = fmaxf(__uint_as_float(g_w1max), 1e-20f) / QMAX;
    const float s_w2 = fmaxf(__uint_as_float(g_w2max), 1e-20f) / QMAX;
    __syncthreads();

    // ---- A tile staging (pure cp.async from quantized x) ----
#pragma unroll
    for (int it = 0; it < 4; it++) {
        int c = tid + it * THREADS;        // 0..1023
        int j = c & 7, half = (c >> 3) & 1, e = c >> 4;
        int node = sids[half * 64 + e];
        int src = node * 128 + j * 16;
        uint32_t dst = e * SA1 + half * 128 + j * 16;
        cp16(sb + SM_A_HI + dst, g_x_hi + src);
        cp16(sb + SM_A_LO + dst, g_x_lo + src);
    }
    cp_commit();
    stage_w(sb, 0, g_w1q_hi, g_w1q_lo, 256, 0, tid);     // W1 k 0..127
    stage_w(sb, 1, g_w1q_hi, g_w1q_lo, 256, 128, tid);   // W1 k 128..255
    cp_wait0();
    __syncthreads();

    int acc1[8][4], acc2[8][4];
#pragma unroll
    for (int j = 0; j < 8; j++)
#pragma unroll
        for (int q = 0; q < 4; q++) { acc1[j][q] = 0; acc2[j][q] = 0; }

    // ---- layer 1 ----
    gemm_chunk(sb, 0, SA1, 0, e0, n0, lane, acc1, acc2);
    __syncthreads();                       // all warps done with buf0
    stage_w(sb, 0, g_w2q_hi, g_w2q_lo, 128, 0, tid);     // W2 -> buf0 (overlaps)
    gemm_chunk(sb, 1, SA1, 128, e0, n0, lane, acc1, acc2);
    __syncthreads();                       // all warps done with A1 + buf1

    // ---- epilogue 1: dequant + bias + elu; per-tile absmax; requantize h1 ----
    const float c1a = 65536.0f * s_x * s_w1;
    const float c2a = 256.0f * s_x * s_w1;
    float vv[8][4];
    float lmax = 0.0f;
#pragma unroll
    for (int nt = 0; nt < 8; nt++) {
        int nc = n0 + 8 * nt + 2 * tig;
#pragma unroll
        for (int q = 0; q < 4; q++) {
            float v = fmaf(c1a, (float)acc1[nt][q], fmaf(c2a, (float)acc2[nt][q],
                           b1s[nc + (q & 1)]));
            v = elu1(v);
            vv[nt][q] = v;
            lmax = fmaxf(lmax, fabsf(v));
        }
    }
#pragma unroll
    for (int o = 16; o > 0; o >>= 1) lmax = fmaxf(lmax, __shfl_xor_sync(0xffffffff, lmax, o));
    if (lane == 0) atomicMax(hmax, __float_as_uint(lmax));
    __syncthreads();
    const float smax = fmaxf(__uint_as_float(hmax[0]), 1e-20f);
    const float inv_s2 = QMAX / smax;
    const float s2 = smax / QMAX;
#pragma unroll
    for (int nt = 0; nt < 8; nt++) {
        int nc = n0 + 8 * nt + 2 * tig;
        int ea = e0 + gid, eb = ea + 8;
        int q00 = quant(vv[nt][0], inv_s2), q01 = quant(vv[nt][1], inv_s2);
        int q10 = quant(vv[nt][2], inv_s2), q11 = quant(vv[nt][3], inv_s2);
        int h0, l0, h1_, l1;
        split16(q00, h0, l0); split16(q01, h1_, l1);
        *reinterpret_cast<uint16_t*>(smem + SM_A_HI + ea * SA2 + nc) =
            (uint16_t)((h0 & 0xFF) | ((h1_ & 0xFF) << 8));
        *reinterpret_cast<uint16_t*>(smem + SM_A_LO + ea * SA2 + nc) =
            (uint16_t)((l0 & 0xFF) | ((l1 & 0xFF) << 8));
        split16(q10, h0, l0); split16(q11, h1_, l1);
        *reinterpret_cast<uint16_t*>(smem + SM_A_HI + eb * SA2 + nc) =
            (uint16_t)((h0 & 0xFF) | ((h1_ & 0xFF) << 8));
        *reinterpret_cast<uint16_t*>(smem + SM_A_LO + eb * SA2 + nc) =
            (uint16_t)((l0 & 0xFF) | ((l1 & 0xFF) << 8));
    }
#pragma unroll
    for (int j = 0; j < 8; j++)
#pragma unroll
        for (int q = 0; q < 4; q++) { acc1[j][q] = 0; acc2[j][q] = 0; }
    cp_wait0();                            // W2 arrived (long ago)
    __syncthreads();                       // h1 visible + W2 visible

    // ---- layer 2 ----
    gemm_chunk(sb, 0, SA2, 0, e0, n0, lane, acc1, acc2);

    // ---- epilogue 2: dequant + bias + elu + dot(W3), butterfly over tig ----
    const float c1b = 65536.0f * s2 * s_w2;
    const float c2b = 256.0f * s2 * s_w2;
    float pa = 0.0f, pb = 0.0f;
#pragma unroll
    for (int nt = 0; nt < 8; nt++) {
        int nc = n0 + 8 * nt + 2 * tig;
        float w0 = w3s[nc], w1 = w3s[nc + 1];
        float v0 = elu1(fmaf(c1b, (float)acc1[nt][0], fmaf(c2b, (float)acc2[nt][0], b2s[nc])));
        float v1 = elu1(fmaf(c1b, (float)acc1[nt][1], fmaf(c2b, (float)acc2[nt][1], b2s[nc + 1])));
        float v2 = elu1(fmaf(c1b, (float)acc1[nt][2], fmaf(c2b, (float)acc2[nt][2], b2s[nc])));
        float v3 = elu1(fmaf(c1b, (float)acc1[nt][3], fmaf(c2b, (float)acc2[nt][3], b2s[nc + 1])));
        pa += v0 * w0 + v1 * w1;
        pb += v2 * w0 + v3 * w1;
    }
    pa += __shfl_xor_sync(0xffffffff, pa, 1);
    pa += __shfl_xor_sync(0xffffffff, pa, 2);
    pb += __shfl_xor_sync(0xffffffff, pb, 1);
    pb += __shfl_xor_sync(0xffffffff, pb, 2);
    float* red = (float*)(smem + (nw ? SM_R1 : SM_R0));
    if (tig == 0) {
        red[e0 + gid] = pa;
        red[e0 + gid + 8] = pb;
    }
    __syncthreads();
    if (tid < 64 && tid < nv) {
        float* r0 = (float*)(smem + SM_R0);
        float* r1 = (float*)(smem + SM_R1);
        out[tile + tid] = r0[tid] + r1[tid] + __ldg(b3);
    }
}

extern "C" void kernel_launch(void* const* d_in, const int* in_sizes, int n_in,
                              void* d_out, int out_size) {
    const float* x  = (const float*)d_in[0];
    const void*  ei = d_in[1];
    const float* W1 = (const float*)d_in[2];
    const float* b1 = (const float*)d_in[3];
    const float* W2 = (const float*)d_in[4];
    const float* b2 = (const float*)d_in[5];
    const float* W3 = (const float*)d_in[6];
    const float* b3 = (const float*)d_in[7];
    float* out = (float*)d_out;

    const int n_edges = out_size;
    const int n_nodes = in_sizes[0] / 128;
    const int n4 = (n_nodes < NMAX ? n_nodes : NMAX) * 128 / 4;

    cudaFuncSetAttribute(edge_mlp_imma_kernel,
                         cudaFuncAttributeMaxDynamicSharedMemorySize, SMEM_BYTES);

    absmax_kernel<<<512, 256>>>(x, n4, W1, W2, (const int*)ei);
    const int qtot = n4 + 8192 + 4096;
    quant_kernel<<<(qtot + 255) / 256, 256>>>(x, n4, W1, W2);
    const int grid = (n_edges + EPT - 1) / EPT;
    edge_mlp_imma_kernel<<<grid, THREADS, SMEM_BYTES>>>(ei, b1, b2, W3, b3,
                                                        out, n_edges, n_nodes);
}

// round 11
// speedup vs baseline: 1.8849x; 1.8849x over previous
#include <cuda_runtime.h>
#include <cuda_bf16.h>
#include <math.h>
#include <stdint.h>

// ---------------------------------------------------------------------------
// EdgeMLPMPN via mma.sync bf16x3-split (hi*hi + hi*lo + lo*hi, fp32 acc).
// R11 = R8 base (650us) + dtype-sniff hoisted to prologue + warp tile
// re-balanced to 2m x 4n (32 edges x 32 ch per warp): LDSM.x4 10 -> 8 per
// k-tile, HMMA unchanged. EPT=64, 2 CTAs/SM, 8 warps (2 mw x 4 nw).
// ---------------------------------------------------------------------------

#define EPT 64
#define THREADS 256
#define NMAX 100000
#define SA1 528   // A1 row stride bytes (256 bf16 + pad); ldmatrix conflict-free
#define SA2 272   // h1 row stride (128 bf16 + pad)
#define SWS 144   // W chunk row stride (64 bf16 + pad)

#define SM_A_HI 0
#define SM_A_LO 33792                  // 64*528
#define SM_W_HI 67584
#define SM_W_LO (SM_W_HI + 18432)      // 128*144
#define SM_CTRL (SM_W_LO + 18432)      // 104448
#define SM_SIDS (SM_CTRL)              // 128 ints
#define SM_B1   (SM_CTRL + 512)
#define SM_B2   (SM_B1 + 512)
#define SM_W3   (SM_B2 + 512)
#define SM_RED  (SM_W3 + 512)          // 4 x 64 floats
#define SMEM_BYTES (SM_RED + 1024)     // ~105KB -> 2 CTAs/SM

__device__ int g_is64;
__device__ __align__(16) __nv_bfloat16 g_x_hi[NMAX * 128];
__device__ __align__(16) __nv_bfloat16 g_x_lo[NMAX * 128];
__device__ __align__(16) __nv_bfloat16 g_w1t_hi[128 * 256];
__device__ __align__(16) __nv_bfloat16 g_w1t_lo[128 * 256];
__device__ __align__(16) __nv_bfloat16 g_w2t_hi[128 * 128];
__device__ __align__(16) __nv_bfloat16 g_w2t_lo[128 * 128];

__device__ __forceinline__ uint32_t smem_u32(const void* p) {
    uint32_t a;
    asm("{ .reg .u64 t; cvta.to.shared.u64 t, %1; cvt.u32.u64 %0, t; }" : "=r"(a) : "l"(p));
    return a;
}
__device__ __forceinline__ void ldm_x4(uint32_t addr, uint32_t r[4]) {
    asm volatile("ldmatrix.sync.aligned.m8n8.x4.shared.b16 {%0,%1,%2,%3}, [%4];"
                 : "=r"(r[0]), "=r"(r[1]), "=r"(r[2]), "=r"(r[3]) : "r"(addr));
}
__device__ __forceinline__ void hmma(float c[4], const uint32_t a[4],
                                     uint32_t b0, uint32_t b1) {
    asm volatile(
        "mma.sync.aligned.m16n8k16.row.col.f32.bf16.bf16.f32 "
        "{%0,%1,%2,%3}, {%4,%5,%6,%7}, {%8,%9}, {%0,%1,%2,%3};"
        : "+f"(c[0]), "+f"(c[1]), "+f"(c[2]), "+f"(c[3])
        : "r"(a[0]), "r"(a[1]), "r"(a[2]), "r"(a[3]), "r"(b0), "r"(b1));
}
__device__ __forceinline__ void cp16(uint32_t dst, const void* src) {
    asm volatile("cp.async.cg.shared.global [%0], [%1], 16;" :: "r"(dst), "l"(src));
}
__device__ __forceinline__ void cp_commit() {
    asm volatile("cp.async.commit_group;" ::: "memory");
}
__device__ __forceinline__ void cp_wait0() {
    asm volatile("cp.async.wait_group 0;" ::: "memory");
}
__device__ __forceinline__ float elu1(float v) { return v > 0.0f ? v : expm1f(v); }
__device__ __forceinline__ void split_bf16(float v, __nv_bfloat16& hi, __nv_bfloat16& lo) {
    hi = __float2bfloat16_rn(v);
    lo = __float2bfloat16_rn(v - __bfloat162float(hi));
}
union BF4 { __nv_bfloat16 b[4]; unsigned long long u; };
union BF2 { __nv_bfloat16 b[2]; uint32_t u; };

// ---------------- prologue A: split x into bf16 hi/lo ----------------
__global__ void xsplit_kernel(const float* __restrict__ x, int n4) {
    int i = blockIdx.x * blockDim.x + threadIdx.x;
    if (i >= n4) return;
    float4 v = __ldg(reinterpret_cast<const float4*>(x) + i);
    BF4 h, l;
    split_bf16(v.x, h.b[0], l.b[0]);
    split_bf16(v.y, h.b[1], l.b[1]);
    split_bf16(v.z, h.b[2], l.b[2]);
    split_bf16(v.w, h.b[3], l.b[3]);
    *reinterpret_cast<unsigned long long*>(g_x_hi + i * 4) = h.u;
    *reinterpret_cast<unsigned long long*>(g_x_lo + i * 4) = l.u;
}

// ---------------- prologue B: transpose + split W1, W2; sniff ei dtype ----
__global__ void wconv_kernel(const float* __restrict__ W1, const float* __restrict__ W2,
                             const int* __restrict__ ei32) {
    int i = blockIdx.x * blockDim.x + threadIdx.x;
    if (i == 0) {
        int odd_or = 0;
#pragma unroll
        for (int j = 1; j < 64; j += 2) odd_or |= ei32[j];
        g_is64 = (odd_or == 0) ? 1 : 0;
    }
    if (i < 32768) {                     // W1T[n][k] <- W1[k][n]
        int n = i >> 8, k = i & 255;
        float v = __ldg(W1 + k * 128 + n);
        __nv_bfloat16 h, l; split_bf16(v, h, l);
        g_w1t_hi[i] = h; g_w1t_lo[i] = l;
    } else if (i < 49152) {              // W2T[n][k] <- W2[k][n]
        int j = i - 32768;
        int n = j >> 7, k = j & 127;
        float v = __ldg(W2 + k * 128 + n);
        __nv_bfloat16 h, l; split_bf16(v, h, l);
        g_w2t_hi[j] = h; g_w2t_lo[j] = l;
    }
}

// async-stage one [128 n][64 k] hi/lo W chunk
__device__ __forceinline__ void stage_w_async(uint32_t sb,
                                              const __nv_bfloat16* __restrict__ gh,
                                              const __nv_bfloat16* __restrict__ gl,
                                              int row_elems, int col0, int tid) {
#pragma unroll
    for (int it = 0; it < 4; it++) {
        int idx = tid + it * THREADS;
        int n = idx >> 3, j = idx & 7;
        cp16(sb + SM_W_HI + n * SWS + j * 16, gh + n * row_elems + col0 + j * 8);
        cp16(sb + SM_W_LO + n * SWS + j * 16, gl + n * row_elems + col0 + j * 8);
    }
    cp_commit();
}

// one 64-k stage (4 k-tiles); warp tile 2m x 4n; pass-major schedule
__device__ __forceinline__ void gemm_stage(uint32_t sb, int sa, int a_k0byte,
                                           int e0, int n0, int lane,
                                           float acc[2][4][4]) {
    const int rowA = lane & 15;
    const int chA = (lane >> 4) * 16;
    const int rowB = (lane & 7) + ((lane >> 4) << 3);
    const int chB = ((lane >> 3) & 1) * 16;

    uint32_t aH0 = sb + SM_A_HI + (e0 + rowA) * sa + chA + a_k0byte;
    uint32_t aH1 = aH0 + 16 * sa;
    uint32_t aL0 = sb + SM_A_LO + (e0 + rowA) * sa + chA + a_k0byte;
    uint32_t aL1 = aL0 + 16 * sa;
    uint32_t bH0 = sb + SM_W_HI + (n0 + rowB) * SWS + chB;
    uint32_t bH1 = bH0 + 16 * SWS;
    uint32_t bL0 = sb + SM_W_LO + (n0 + rowB) * SWS + chB;
    uint32_t bL1 = bL0 + 16 * SWS;

#pragma unroll
    for (int kt = 0; kt < 4; kt++) {
        uint32_t ah0[4], ah1[4], al0[4], al1[4];
        ldm_x4(aH0 + kt * 32, ah0);
        ldm_x4(aH1 + kt * 32, ah1);
        ldm_x4(aL0 + kt * 32, al0);
        ldm_x4(aL1 + kt * 32, al1);
        uint32_t bh0[4], bh1[4], bl0[4], bl1[4];
        ldm_x4(bH0 + kt * 32, bh0);    // n-tiles 0,1 hi
        ldm_x4(bH1 + kt * 32, bh1);    // n-tiles 2,3 hi
        ldm_x4(bL0 + kt * 32, bl0);
        ldm_x4(bL1 + kt * 32, bl1);
        // pass hh
        hmma(acc[0][0], ah0, bh0[0], bh0[1]);
        hmma(acc[0][1], ah0, bh0[2], bh0[3]);
        hmma(acc[0][2], ah0, bh1[0], bh1[1]);
        hmma(acc[0][3], ah0, bh1[2], bh1[3]);
        hmma(acc[1][0], ah1, bh0[0], bh0[1]);
        hmma(acc[1][1], ah1, bh0[2], bh0[3]);
        hmma(acc[1][2], ah1, bh1[0], bh1[1]);
        hmma(acc[1][3], ah1, bh1[2], bh1[3]);
        // pass hl
        hmma(acc[0][0], ah0, bl0[0], bl0[1]);
        hmma(acc[0][1], ah0, bl0[2], bl0[3]);
        hmma(acc[0][2], ah0, bl1[0], bl1[1]);
        hmma(acc[0][3], ah0, bl1[2], bl1[3]);
        hmma(acc[1][0], ah1, bl0[0], bl0[1]);
        hmma(acc[1][1], ah1, bl0[2], bl0[3]);
        hmma(acc[1][2], ah1, bl1[0], bl1[1]);
        hmma(acc[1][3], ah1, bl1[2], bl1[3]);
        // pass lh
        hmma(acc[0][0], al0, bh0[0], bh0[1]);
        hmma(acc[0][1], al0, bh0[2], bh0[3]);
        hmma(acc[0][2], al0, bh1[0], bh1[1]);
        hmma(acc[0][3], al0, bh1[2], bh1[3]);
        hmma(acc[1][0], al1, bh0[0], bh0[1]);
        hmma(acc[1][1], al1, bh0[2], bh0[3]);
        hmma(acc[1][2], al1, bh1[0], bh1[1]);
        hmma(acc[1][3], al1, bh1[2], bh1[3]);
    }
}

__global__ void __launch_bounds__(THREADS, 2)
edge_mlp_hmma_kernel(const void* __restrict__ ei,
                     const float* __restrict__ b1, const float* __restrict__ b2,
                     const float* __restrict__ W3, const float* __restrict__ b3,
                     float* __restrict__ out, int n_edges, int n_nodes) {
    extern __shared__ char smem[];
    const uint32_t sb = smem_u32(smem);
    const int tid = threadIdx.x, wid = tid >> 5, lane = tid & 31;
    const int gid = lane >> 2, tig = lane & 3;
    const int mw = wid >> 2, nw = wid & 3;     // 2 x 4 warp grid
    const int e0 = mw * 32, n0 = nw * 32;
    const int tile = blockIdx.x * EPT;
    const int nv = min(EPT, n_edges - tile);

    const bool is64 = (g_is64 != 0);
    const int* ei32 = (const int*)ei;
    const long long* ei64 = (const long long*)ei;

    int* sids = (int*)(smem + SM_SIDS);
    float* b1s = (float*)(smem + SM_B1);
    float* b2s = (float*)(smem + SM_B2);
    float* w3s = (float*)(smem + SM_W3);
    const int ncl = min(n_nodes, NMAX);
    if (tid < 128) {
        int half = tid >> 6, e = tid & 63;
        int ec = e < nv ? e : (nv - 1);
        int pos = half * n_edges + tile + ec;
        long long node = is64 ? ei64[pos] : (long long)ei32[pos];
        node = node < 0 ? 0 : (node >= ncl ? (long long)ncl - 1 : node);
        sids[tid] = (int)node;
        b1s[tid] = __ldg(b1 + tid);
        b2s[tid] = __ldg(b2 + tid);
        w3s[tid] = __ldg(W3 + tid);
    }
    __syncthreads();

    // ---- A tile staging: pure cp.async from precomputed g_x_hi/lo ----
#pragma unroll
    for (int it = 0; it < 8; it++) {
        int c = tid + it * THREADS;        // 0..2047
        int j = c & 15, half = (c >> 4) & 1, e = c >> 5;
        int node = sids[half * 64 + e];
        int src = node * 128 + j * 8;
        uint32_t dst = e * SA1 + half * 256 + j * 16;
        cp16(sb + SM_A_HI + dst, g_x_hi + src);
        cp16(sb + SM_A_LO + dst, g_x_lo + src);
    }
    cp_commit();

    // prefetch W1 chunk 0 (own commit group)
    stage_w_async(sb, g_w1t_hi, g_w1t_lo, 256, 0, tid);

    cp_wait0();
    __syncthreads();

    float acc[2][4][4];
#pragma unroll
    for (int m = 0; m < 2; m++)
#pragma unroll
        for (int j = 0; j < 4; j++)
#pragma unroll
            for (int q = 0; q < 4; q++) acc[m][j][q] = 0.0f;

    // ---- layer 1: four 64-k stages ----
#pragma unroll 1
    for (int c = 0; c < 4; c++) {
        gemm_stage(sb, SA1, c * 128, e0, n0, lane, acc);
        __syncthreads();
        if (c < 3) {
            stage_w_async(sb, g_w1t_hi, g_w1t_lo, 256, (c + 1) * 64, tid);
            cp_wait0();
            __syncthreads();
        }
    }

    // prefetch W2 chunk 0; overlap with epilogue-1 resplit
    stage_w_async(sb, g_w2t_hi, g_w2t_lo, 128, 0, tid);

    // ---- epilogue 1: bias + elu, re-split h1 into A region (stride SA2) ----
#pragma unroll
    for (int mt = 0; mt < 2; mt++) {
#pragma unroll
        for (int nt = 0; nt < 4; nt++) {
            int nc = n0 + 8 * nt + 2 * tig;
            int ea = e0 + 16 * mt + gid, eb = ea + 8;
            float v00 = elu1(acc[mt][nt][0] + b1s[nc]);
            float v01 = elu1(acc[mt][nt][1] + b1s[nc + 1]);
            float v10 = elu1(acc[mt][nt][2] + b1s[nc]);
            float v11 = elu1(acc[mt][nt][3] + b1s[nc + 1]);
            BF2 h, l;
            split_bf16(v00, h.b[0], l.b[0]);
            split_bf16(v01, h.b[1], l.b[1]);
            *reinterpret_cast<uint32_t*>(smem + SM_A_HI + ea * SA2 + nc * 2) = h.u;
            *reinterpret_cast<uint32_t*>(smem + SM_A_LO + ea * SA2 + nc * 2) = l.u;
            split_bf16(v10, h.b[0], l.b[0]);
            split_bf16(v11, h.b[1], l.b[1]);
            *reinterpret_cast<uint32_t*>(smem + SM_A_HI + eb * SA2 + nc * 2) = h.u;
            *reinterpret_cast<uint32_t*>(smem + SM_A_LO + eb * SA2 + nc * 2) = l.u;
        }
    }
#pragma unroll
    for (int m = 0; m < 2; m++)
#pragma unroll
        for (int j = 0; j < 4; j++)
#pragma unroll
            for (int q = 0; q < 4; q++) acc[m][j][q] = 0.0f;
    cp_wait0();
    __syncthreads();

    // ---- layer 2: two 64-k stages ----
#pragma unroll 1
    for (int c = 0; c < 2; c++) {
        gemm_stage(sb, SA2, c * 128, e0, n0, lane, acc);
        __syncthreads();
        if (c == 0) {
            stage_w_async(sb, g_w2t_hi, g_w2t_lo, 128, 64, tid);
            cp_wait0();
            __syncthreads();
        }
    }

    // ---- epilogue 2: bias + elu + dot(W3), butterfly over tig ----
    float pa[2] = {0.0f, 0.0f}, pb[2] = {0.0f, 0.0f};
#pragma unroll
    for (int mt = 0; mt < 2; mt++) {
#pragma unroll
        for (int nt = 0; nt < 4; nt++) {
            int nc = n0 + 8 * nt + 2 * tig;
            float w0 = w3s[nc], w1 = w3s[nc + 1];
            pa[mt] += elu1(acc[mt][nt][0] + b2s[nc]) * w0
                    + elu1(acc[mt][nt][1] + b2s[nc + 1]) * w1;
            pb[mt] += elu1(acc[mt][nt][2] + b2s[nc]) * w0
                    + elu1(acc[mt][nt][3] + b2s[nc + 1]) * w1;
        }
    }
#pragma unroll
    for (int mt = 0; mt < 2; mt++) {
        pa[mt] += __shfl_xor_sync(0xffffffff, pa[mt], 1);
        pa[mt] += __shfl_xor_sync(0xffffffff, pa[mt], 2);
        pb[mt] += __shfl_xor_sync(0xffffffff, pb[mt], 1);
        pb[mt] += __shfl_xor_sync(0xffffffff, pb[mt], 2);
    }
    float* red = (float*)(smem + SM_RED) + nw * 64;
    if (tig == 0) {
#pragma unroll
        for (int mt = 0; mt < 2; mt++) {
            red[e0 + 16 * mt + gid] = pa[mt];
            red[e0 + 16 * mt + gid + 8] = pb[mt];
        }
    }
    __syncthreads();
    if (tid < 64 && tid < nv) {
        float* r = (float*)(smem + SM_RED);
        out[tile + tid] = r[tid] + r[64 + tid] + r[128 + tid] + r[192 + tid] + __ldg(b3);
    }
}

extern "C" void kernel_launch(void* const* d_in, const int* in_sizes, int n_in,
                              void* d_out, int out_size) {
    const float* x  = (const float*)d_in[0];
    const void*  ei = d_in[1];
    const float* W1 = (const float*)d_in[2];
    const float* b1 = (const float*)d_in[3];
    const float* W2 = (const float*)d_in[4];
    const float* b2 = (const float*)d_in[5];
    const float* W3 = (const float*)d_in[6];
    const float* b3 = (const float*)d_in[7];
    float* out = (float*)d_out;

    const int n_edges = out_size;
    const int n_nodes = in_sizes[0] / 128;
    const int n4 = (n_nodes < NMAX ? n_nodes : NMAX) * 128 / 4;

    cudaFuncSetAttribute(edge_mlp_hmma_kernel,
                         cudaFuncAttributeMaxDynamicSharedMemorySize, SMEM_BYTES);

    wconv_kernel<<<192, 256>>>(W1, W2, (const int*)ei);
    xsplit_kernel<<<(n4 + 255) / 256, 256>>>(x, n4);
    const int grid = (n_edges + EPT - 1) / EPT;
    edge_mlp_hmma_kernel<<<grid, THREADS, SMEM_BYTES>>>(ei, b1, b2, W3, b3,
                                                        out, n_edges, n_nodes);
}